// round 11
// baseline (speedup 1.0000x reference)
#include <cuda_runtime.h>

// _QuantumLSTMCell: analytic collapse of the 4-qubit circuit.
// angles = comb @ W^T + b ; z_w = cos(angle_w + th_w)
// E0 = z1 z2 z3 ; E1 = z0 z1 ; E2 = z0 z1 z2 ; E3 = z0 z1 z2 z3
// f,i,o = sigmoid(E), g = tanh(E_u); c' = f*cx + i*g; h' = o*tanh(c')
// out = [h_new (B*4) | c_new (B*4)]
//
// R11: j-split tiling. Thread (g=lane>>2, q=lane&3) owns gate q for rows
// {g, g+8} of its warp's 16-row block. 4x warp count (50% occ), 4x less fma
// per thread, quad-broadcast weight LDS, conflict-free x LDS, single launch.

#define THREADS 128
#define WARPS 4
#define RPT 2                       // rows per thread
#define ROWS_WARP 16
#define ROWS_BLK (WARPS * ROWS_WARP) // 64
#define D_COLS 256
#define NJ 16
#define TILE_K 16
#define NTILES (D_COLS / TILE_K)    // 16
#define PITCH 20                    // floats per staged row
#define STAGE_F (ROWS_WARP * PITCH) // 320 floats per warp-stage
#define NKP 130                     // 260/2 k-pairs

typedef unsigned long long u64;

__device__ __forceinline__ u64 pk(float lo, float hi) {
    u64 r; asm("mov.b64 %0, {%1,%2};" : "=l"(r) : "f"(lo), "f"(hi)); return r;
}
__device__ __forceinline__ void upk(u64 v, float& lo, float& hi) {
    asm("mov.b64 {%0,%1}, %2;" : "=f"(lo), "=f"(hi) : "l"(v));
}
__device__ __forceinline__ void fma2(u64& d, u64 a, u64 b) {
    asm("fma.rn.f32x2 %0, %1, %2, %0;" : "+l"(d) : "l"(a), "l"(b));
}
__device__ __forceinline__ void cp16(unsigned dst, const void* src) {
    asm volatile("cp.async.cg.shared.global [%0], [%1], 16;" :: "r"(dst), "l"(src));
}
__device__ __forceinline__ void cp_commit() {
    asm volatile("cp.async.commit_group;");
}
__device__ __forceinline__ void cp_wait1() {
    asm volatile("cp.async.wait_group 1;");
}
__device__ __forceinline__ void cp_wait0() {
    asm volatile("cp.async.wait_group 0;");
}

__device__ __forceinline__ float sigmoidf_(float x) {
    return 1.0f / (1.0f + __expf(-x));
}
__device__ __forceinline__ float tanhf_(float x) {
    return 1.0f - 2.0f / (__expf(2.0f * x) + 1.0f);
}

// issue one TILE_K=16 tile (16 rows x 64 B) for this warp: 2 cp16/lane
__device__ __forceinline__ void issue_tile(unsigned xs_s, const float* xw,
                                           int lane, int tile, int slot) {
#pragma unroll
    for (int i = 0; i < 2; i++) {
        int rl = i * 8 + (lane >> 2);
        int ch = lane & 3;
        cp16(xs_s + (unsigned)((slot * STAGE_F + rl * PITCH + ch * 4) * 4),
             xw + (size_t)rl * D_COLS + tile * TILE_K + ch * 4);
    }
    cp_commit();
}

__global__ void __launch_bounds__(THREADS, 8)
qlstm_kernel(const float* __restrict__ x, const float* __restrict__ hx,
             const float* __restrict__ cx,
             const float* __restrict__ Wf, const float* __restrict__ Wi,
             const float* __restrict__ Wu, const float* __restrict__ Wo,
             const float* __restrict__ bf, const float* __restrict__ bi,
             const float* __restrict__ bu, const float* __restrict__ bo,
             const float* __restrict__ tf, const float* __restrict__ ti,
             const float* __restrict__ tu, const float* __restrict__ to,
             float* __restrict__ out, int B)
{
    // weights: sw[kp*16 + j] = (W_j[2kp], W_j[2kp+1]) packed, j = gate*4+wire
    __shared__ __align__(16) u64 sw[NKP * NJ];                 // 16,640 B
    __shared__ __align__(16) float xs[WARPS * 2 * STAGE_F];    // 10,240 B
    __shared__ float sphase[NJ];

    const int tid  = threadIdx.x;
    const int wid  = tid >> 5;
    const int lane = tid & 31;
    const int g    = lane >> 2;       // row group 0..7
    const int q    = lane & 3;        // gate 0..3

    const int warpRow0 = blockIdx.x * ROWS_BLK + wid * ROWS_WARP;
    const float* xw = x + (size_t)warpRow0 * D_COLS;

    float* xs_w = xs + wid * (2 * STAGE_F);
    unsigned xs_s = (unsigned)__cvta_generic_to_shared(xs_w);

    // ---- prologue: tiles 0,1 ----
    issue_tile(xs_s, xw, lane, 0, 0);
    issue_tile(xs_s, xw, lane, 1, 1);

    // ---- stage weights (once per block) ----
    for (int i = tid; i < NKP * NJ; i += THREADS) {
        int kp = i >> 4, j = i & 15;
        int gate = j >> 2, wire = j & 3;
        const float* W = (gate == 0) ? Wf : (gate == 1) ? Wi
                       : (gate == 2) ? Wu : Wo;
        const float* row = W + wire * 260 + 2 * kp;
        sw[i] = pk(row[0], row[1]);
    }
    if (tid < NJ) {
        int j = tid, gate = j >> 2, wire = j & 3;
        const float* bb = (gate == 0) ? bf : (gate == 1) ? bi
                        : (gate == 2) ? bu : bo;
        const float* tt = (gate == 0) ? tf : (gate == 1) ? ti
                        : (gate == 2) ? tu : to;
        sphase[j] = bb[wire] + tt[wire];
    }
    __syncthreads();   // the ONLY block barrier

    const ulonglong2* swv = (const ulonglong2*)sw;   // idx: kp*8 + q*2 + h

    u64 acc[RPT][4];
#pragma unroll
    for (int i = 0; i < RPT; i++)
#pragma unroll
        for (int jj = 0; jj < 4; jj++) acc[i][jj] = 0ull;

    // ---- warp-private pipelined main loop ----
#pragma unroll 1
    for (int t = 0; t < NTILES; t++) {
        if (t == NTILES - 1) cp_wait0(); else cp_wait1();
        __syncwarp();

        const float* xb = xs_w + (t & 1) * STAGE_F;
#pragma unroll
        for (int kq = 0; kq < 4; kq++) {
            // x pairs for this thread's 2 rows (rows g, g+8): 2x LDS.128
            ulonglong2 x0 = *(const ulonglong2*)(xb + g * PITCH + kq * 4);
            ulonglong2 x1 = *(const ulonglong2*)(xb + (g + 8) * PITCH + kq * 4);
            int kp0 = t * 8 + kq * 2;
            const ulonglong2* wp = swv + (size_t)kp0 * 8 + q * 2;
            ulonglong2 a0 = wp[0], b0 = wp[1];    // kp0: j q*4 + 0..3
            ulonglong2 a1 = wp[8], b1 = wp[9];    // kp1
            fma2(acc[0][0], x0.x, a0.x); fma2(acc[0][1], x0.x, a0.y);
            fma2(acc[0][2], x0.x, b0.x); fma2(acc[0][3], x0.x, b0.y);
            fma2(acc[1][0], x1.x, a0.x); fma2(acc[1][1], x1.x, a0.y);
            fma2(acc[1][2], x1.x, b0.x); fma2(acc[1][3], x1.x, b0.y);
            fma2(acc[0][0], x0.y, a1.x); fma2(acc[0][1], x0.y, a1.y);
            fma2(acc[0][2], x0.y, b1.x); fma2(acc[0][3], x0.y, b1.y);
            fma2(acc[1][0], x1.y, a1.x); fma2(acc[1][1], x1.y, a1.y);
            fma2(acc[1][2], x1.y, b1.x); fma2(acc[1][3], x1.y, b1.y);
        }
        __syncwarp();

        if (t + 2 < NTILES)
            issue_tile(xs_s, xw, lane, t + 2, t & 1);
    }

    // ---- hx tail: k 256..259 = kp 128,129 ----
    {
        ulonglong2 h0 = ((const ulonglong2*)hx)[warpRow0 + g];
        ulonglong2 h1 = ((const ulonglong2*)hx)[warpRow0 + g + 8];
        const ulonglong2* wp = swv + (size_t)128 * 8 + q * 2;
        ulonglong2 a0 = wp[0], b0 = wp[1];
        ulonglong2 a1 = wp[8], b1 = wp[9];
        fma2(acc[0][0], h0.x, a0.x); fma2(acc[0][1], h0.x, a0.y);
        fma2(acc[0][2], h0.x, b0.x); fma2(acc[0][3], h0.x, b0.y);
        fma2(acc[1][0], h1.x, a0.x); fma2(acc[1][1], h1.x, a0.y);
        fma2(acc[1][2], h1.x, b0.x); fma2(acc[1][3], h1.x, b0.y);
        fma2(acc[0][0], h0.y, a1.x); fma2(acc[0][1], h0.y, a1.y);
        fma2(acc[0][2], h0.y, b1.x); fma2(acc[0][3], h0.y, b1.y);
        fma2(acc[1][0], h1.y, a1.x); fma2(acc[1][1], h1.y, a1.y);
        fma2(acc[1][2], h1.y, b1.x); fma2(acc[1][3], h1.y, b1.y);
    }

    // ---- epilogue: gate-local E + activation, quad exchange via smem ----
    float4 ph = ((const float4*)sphase)[q];
    float* eb = xs_w;   // reuse warp-private x stage (>= 16*17 floats)

#pragma unroll
    for (int i = 0; i < RPT; i++) {
        int rl = g + 8 * i;
        float lo, hi;
        upk(acc[i][0], lo, hi); float z0 = __cosf(lo + hi + ph.x);
        upk(acc[i][1], lo, hi); float z1 = __cosf(lo + hi + ph.y);
        upk(acc[i][2], lo, hi); float z2 = __cosf(lo + hi + ph.z);
        upk(acc[i][3], lo, hi); float z3 = __cosf(lo + hi + ph.w);
        float p01 = z0 * z1;
        float E0 = z1 * z2 * z3;
        float E1 = p01;
        float E2 = p01 * z2;
        float E3 = p01 * z2 * z3;
        // gate 2 (u) -> tanh, others -> sigmoid
        float a0 = (q == 2) ? tanhf_(E0) : sigmoidf_(E0);
        float a1 = (q == 2) ? tanhf_(E1) : sigmoidf_(E1);
        float a2 = (q == 2) ? tanhf_(E2) : sigmoidf_(E2);
        float a3 = (q == 2) ? tanhf_(E3) : sigmoidf_(E3);
        eb[rl * 17 + q * 4 + 0] = a0;
        eb[rl * 17 + q * 4 + 1] = a1;
        eb[rl * 17 + q * 4 + 2] = a2;
        eb[rl * 17 + q * 4 + 3] = a3;
    }
    __syncwarp();

#pragma unroll
    for (int i = 0; i < RPT; i++) {
        int rl = g + 8 * i;
        int row = warpRow0 + rl;
        float fv = eb[rl * 17 + 0  + q];
        float iv = eb[rl * 17 + 4  + q];
        float uv = eb[rl * 17 + 8  + q];
        float ov = eb[rl * 17 + 12 + q];
        float cxv = cx[(size_t)row * 4 + q];
        float c = fv * cxv + iv * uv;
        float h = ov * tanhf_(c);
        out[(size_t)row * 4 + q] = h;
        out[(size_t)B * 4 + (size_t)row * 4 + q] = c;
    }
}

extern "C" void kernel_launch(void* const* d_in, const int* in_sizes, int n_in,
                              void* d_out, int out_size) {
    const float* x  = (const float*)d_in[0];
    const float* hx = (const float*)d_in[1];
    const float* cx = (const float*)d_in[2];
    const float* Wf = (const float*)d_in[3];
    const float* bf = (const float*)d_in[4];
    const float* Wi = (const float*)d_in[5];
    const float* bi = (const float*)d_in[6];
    const float* Wu = (const float*)d_in[7];
    const float* bu = (const float*)d_in[8];
    const float* Wo = (const float*)d_in[9];
    const float* bo = (const float*)d_in[10];
    const float* tf = (const float*)d_in[11];
    const float* ti = (const float*)d_in[12];
    const float* tu = (const float*)d_in[13];
    const float* to = (const float*)d_in[14];
    float* out = (float*)d_out;

    int B = in_sizes[0] / D_COLS;                 // 131072
    int grid = (B + ROWS_BLK - 1) / ROWS_BLK;     // 2048

    qlstm_kernel<<<grid, THREADS>>>(x, hx, cx, Wf, Wi, Wu, Wo,
                                    bf, bi, bu, bo,
                                    tf, ti, tu, to, out, B);
}

// round 12
// speedup vs baseline: 1.0660x; 1.0660x over previous
#include <cuda_runtime.h>

// _QuantumLSTMCell: analytic collapse of the 4-qubit circuit.
// angles = comb @ W^T + b ; z_w = cos(angle_w + th_w)
// E0 = z1 z2 z3 ; E1 = z0 z1 ; E2 = z0 z1 z2 ; E3 = z0 z1 z2 z3
// f,i,o = sigmoid(E), g = tanh(E_u); c' = f*cx + i*g; h' = o*tanh(c')
// out = [h_new (B*4) | c_new (B*4)]
//
// R12: j-split (thread owns gate q) + RPT=4 rows per thread: keeps R11's
// occupancy (24 warps/SM) while restoring weight-load amortization
// (8 LDS per 32 fma2). Warp-private cp.async pipeline, single launch.

#define THREADS 128
#define WARPS 4
#define RPT 4                       // rows per thread
#define ROWS_WARP 32
#define ROWS_BLK (WARPS * ROWS_WARP) // 128
#define D_COLS 256
#define NJ 16
#define TILE_K 16
#define NTILES (D_COLS / TILE_K)    // 16
#define PITCH 20                    // floats per staged row
#define STAGE_F (ROWS_WARP * PITCH) // 640 floats per warp-stage
#define NKP 130                     // 260/2 k-pairs

typedef unsigned long long u64;

__device__ __forceinline__ u64 pk(float lo, float hi) {
    u64 r; asm("mov.b64 %0, {%1,%2};" : "=l"(r) : "f"(lo), "f"(hi)); return r;
}
__device__ __forceinline__ void upk(u64 v, float& lo, float& hi) {
    asm("mov.b64 {%0,%1}, %2;" : "=f"(lo), "=f"(hi) : "l"(v));
}
__device__ __forceinline__ void fma2(u64& d, u64 a, u64 b) {
    asm("fma.rn.f32x2 %0, %1, %2, %0;" : "+l"(d) : "l"(a), "l"(b));
}
__device__ __forceinline__ void cp16(unsigned dst, const void* src) {
    asm volatile("cp.async.cg.shared.global [%0], [%1], 16;" :: "r"(dst), "l"(src));
}
__device__ __forceinline__ void cp_commit() {
    asm volatile("cp.async.commit_group;");
}
__device__ __forceinline__ void cp_wait1() {
    asm volatile("cp.async.wait_group 1;");
}
__device__ __forceinline__ void cp_wait0() {
    asm volatile("cp.async.wait_group 0;");
}

__device__ __forceinline__ float sigmoidf_(float x) {
    return 1.0f / (1.0f + __expf(-x));
}
__device__ __forceinline__ float tanhf_(float x) {
    return 1.0f - 2.0f / (__expf(2.0f * x) + 1.0f);
}

// issue one TILE_K=16 tile (32 rows x 64 B) for this warp: 4 cp16/lane.
// STS banks: granule (rl*5 + ch) mod 8 = perm(g)*1 + ch -> conflict-free.
__device__ __forceinline__ void issue_tile(unsigned xs_s, const float* xw,
                                           int lane, int tile, int slot) {
#pragma unroll
    for (int i = 0; i < 4; i++) {
        int rl = i * 8 + (lane >> 2);
        int ch = lane & 3;
        cp16(xs_s + (unsigned)((slot * STAGE_F + rl * PITCH + ch * 4) * 4),
             xw + (size_t)rl * D_COLS + tile * TILE_K + ch * 4);
    }
    cp_commit();
}

__global__ void __launch_bounds__(THREADS, 6)
qlstm_kernel(const float* __restrict__ x, const float* __restrict__ hx,
             const float* __restrict__ cx,
             const float* __restrict__ Wf, const float* __restrict__ Wi,
             const float* __restrict__ Wu, const float* __restrict__ Wo,
             const float* __restrict__ bf, const float* __restrict__ bi,
             const float* __restrict__ bu, const float* __restrict__ bo,
             const float* __restrict__ tf, const float* __restrict__ ti,
             const float* __restrict__ tu, const float* __restrict__ to,
             float* __restrict__ out, int B)
{
    // weights: sw[kp*16 + j] = (W_j[2kp], W_j[2kp+1]) packed, j = gate*4+wire
    __shared__ __align__(16) u64 sw[NKP * NJ];                 // 16,640 B
    __shared__ __align__(16) float xs[WARPS * 2 * STAGE_F];    // 20,480 B
    __shared__ float sphase[NJ];

    const int tid  = threadIdx.x;
    const int wid  = tid >> 5;
    const int lane = tid & 31;
    const int g    = lane >> 2;       // row group 0..7
    const int q    = lane & 3;        // gate 0..3

    const int warpRow0 = blockIdx.x * ROWS_BLK + wid * ROWS_WARP;
    const float* xw = x + (size_t)warpRow0 * D_COLS;

    float* xs_w = xs + wid * (2 * STAGE_F);
    unsigned xs_s = (unsigned)__cvta_generic_to_shared(xs_w);

    // ---- prologue: tiles 0,1 ----
    issue_tile(xs_s, xw, lane, 0, 0);
    issue_tile(xs_s, xw, lane, 1, 1);

    // ---- stage weights (once per block) ----
    for (int i = tid; i < NKP * NJ; i += THREADS) {
        int kp = i >> 4, j = i & 15;
        int gate = j >> 2, wire = j & 3;
        const float* W = (gate == 0) ? Wf : (gate == 1) ? Wi
                       : (gate == 2) ? Wu : Wo;
        const float* row = W + wire * 260 + 2 * kp;
        sw[i] = pk(row[0], row[1]);
    }
    if (tid < NJ) {
        int j = tid, gate = j >> 2, wire = j & 3;
        const float* bb = (gate == 0) ? bf : (gate == 1) ? bi
                        : (gate == 2) ? bu : bo;
        const float* tt = (gate == 0) ? tf : (gate == 1) ? ti
                        : (gate == 2) ? tu : to;
        sphase[j] = bb[wire] + tt[wire];
    }
    __syncthreads();   // the ONLY block barrier

    const ulonglong2* swv = (const ulonglong2*)sw;   // idx: kp*8 + q*2 + h

    u64 acc[RPT][4];
#pragma unroll
    for (int i = 0; i < RPT; i++)
#pragma unroll
        for (int jj = 0; jj < 4; jj++) acc[i][jj] = 0ull;

    // ---- warp-private pipelined main loop ----
#pragma unroll 1
    for (int t = 0; t < NTILES; t++) {
        if (t == NTILES - 1) cp_wait0(); else cp_wait1();
        __syncwarp();

        const float* xb = xs_w + (t & 1) * STAGE_F;
#pragma unroll
        for (int kq = 0; kq < 4; kq++) {
            ulonglong2 xv[RPT];                       // 4 rows x 2 k-pairs
#pragma unroll
            for (int i = 0; i < RPT; i++)
                xv[i] = *(const ulonglong2*)(xb + (g + 8 * i) * PITCH + kq * 4);
            int kp0 = t * 8 + kq * 2;
            const ulonglong2* wp = swv + (size_t)kp0 * 8 + q * 2;
            ulonglong2 a0 = wp[0], b0 = wp[1];        // kp0: j = q*4 + 0..3
            ulonglong2 a1 = wp[8], b1 = wp[9];        // kp1
#pragma unroll
            for (int i = 0; i < RPT; i++) {
                fma2(acc[i][0], xv[i].x, a0.x); fma2(acc[i][1], xv[i].x, a0.y);
                fma2(acc[i][2], xv[i].x, b0.x); fma2(acc[i][3], xv[i].x, b0.y);
                fma2(acc[i][0], xv[i].y, a1.x); fma2(acc[i][1], xv[i].y, a1.y);
                fma2(acc[i][2], xv[i].y, b1.x); fma2(acc[i][3], xv[i].y, b1.y);
            }
        }
        __syncwarp();

        if (t + 2 < NTILES)
            issue_tile(xs_s, xw, lane, t + 2, t & 1);
    }

    // ---- hx tail: k 256..259 = kp 128,129 ----
    {
        const ulonglong2* wp = swv + (size_t)128 * 8 + q * 2;
        ulonglong2 a0 = wp[0], b0 = wp[1];
        ulonglong2 a1 = wp[8], b1 = wp[9];
#pragma unroll
        for (int i = 0; i < RPT; i++) {
            ulonglong2 hv = ((const ulonglong2*)hx)[warpRow0 + g + 8 * i];
            fma2(acc[i][0], hv.x, a0.x); fma2(acc[i][1], hv.x, a0.y);
            fma2(acc[i][2], hv.x, b0.x); fma2(acc[i][3], hv.x, b0.y);
            fma2(acc[i][0], hv.y, a1.x); fma2(acc[i][1], hv.y, a1.y);
            fma2(acc[i][2], hv.y, b1.x); fma2(acc[i][3], hv.y, b1.y);
        }
    }

    // ---- epilogue: gate-local E + activation, quad exchange via smem ----
    float4 ph = ((const float4*)sphase)[q];
    float* eb = xs_w;   // reuse warp-private x stage (needs 32*17=544 <= 1280)

#pragma unroll
    for (int i = 0; i < RPT; i++) {
        int rl = g + 8 * i;
        float lo, hi;
        upk(acc[i][0], lo, hi); float z0 = __cosf(lo + hi + ph.x);
        upk(acc[i][1], lo, hi); float z1 = __cosf(lo + hi + ph.y);
        upk(acc[i][2], lo, hi); float z2 = __cosf(lo + hi + ph.z);
        upk(acc[i][3], lo, hi); float z3 = __cosf(lo + hi + ph.w);
        float p01 = z0 * z1;
        float E0 = z1 * z2 * z3;
        float E1 = p01;
        float E2 = p01 * z2;
        float E3 = p01 * z2 * z3;
        // gate 2 (u) -> tanh, others -> sigmoid
        float a0 = (q == 2) ? tanhf_(E0) : sigmoidf_(E0);
        float a1 = (q == 2) ? tanhf_(E1) : sigmoidf_(E1);
        float a2 = (q == 2) ? tanhf_(E2) : sigmoidf_(E2);
        float a3 = (q == 2) ? tanhf_(E3) : sigmoidf_(E3);
        eb[rl * 17 + q * 4 + 0] = a0;
        eb[rl * 17 + q * 4 + 1] = a1;
        eb[rl * 17 + q * 4 + 2] = a2;
        eb[rl * 17 + q * 4 + 3] = a3;
    }
    __syncwarp();

#pragma unroll
    for (int i = 0; i < RPT; i++) {
        int rl = g + 8 * i;
        int row = warpRow0 + rl;
        float fv = eb[rl * 17 + 0  + q];
        float iv = eb[rl * 17 + 4  + q];
        float uv = eb[rl * 17 + 8  + q];
        float ov = eb[rl * 17 + 12 + q];
        float cxv = cx[(size_t)row * 4 + q];
        float c = fv * cxv + iv * uv;
        float h = ov * tanhf_(c);
        out[(size_t)row * 4 + q] = h;
        out[(size_t)B * 4 + (size_t)row * 4 + q] = c;
    }
}

extern "C" void kernel_launch(void* const* d_in, const int* in_sizes, int n_in,
                              void* d_out, int out_size) {
    const float* x  = (const float*)d_in[0];
    const float* hx = (const float*)d_in[1];
    const float* cx = (const float*)d_in[2];
    const float* Wf = (const float*)d_in[3];
    const float* bf = (const float*)d_in[4];
    const float* Wi = (const float*)d_in[5];
    const float* bi = (const float*)d_in[6];
    const float* Wu = (const float*)d_in[7];
    const float* bu = (const float*)d_in[8];
    const float* Wo = (const float*)d_in[9];
    const float* bo = (const float*)d_in[10];
    const float* tf = (const float*)d_in[11];
    const float* ti = (const float*)d_in[12];
    const float* tu = (const float*)d_in[13];
    const float* to = (const float*)d_in[14];
    float* out = (float*)d_out;

    int B = in_sizes[0] / D_COLS;                 // 131072
    int grid = (B + ROWS_BLK - 1) / ROWS_BLK;     // 1024

    qlstm_kernel<<<grid, THREADS>>>(x, hx, cx, Wf, Wi, Wu, Wo,
                                    bf, bi, bu, bo,
                                    tf, ti, tu, to, out, B);
}